// round 11
// baseline (speedup 1.0000x reference)
#include <cuda_runtime.h>
#include <cuda_bf16.h>
#include <cstdint>

#define IN_FEAT   256
#define OUT_FEAT  32
#define MAXN      102400
#define CAP       64             // bucket slots per row (avg degree 16)
#define MAXOVF    8192
#define TM        256
#define NT        256
#define KCH       32             // k-floats per staged chunk
#define NCHUNK    (IN_FEAT / KCH)   // 8
#define SFP       36
#define KP        260
#define SWT_ELEMS (OUT_FEAT * KP)
#define SF_ELEMS  (TM * SFP)
#define SMEM_BYTES ((SWT_ELEMS + 2 * SF_ELEMS) * 4)   // ~105 KB

__device__ float g_x[MAXN * OUT_FEAT];          // projected features (13 MB)
__device__ int   g_cnt[MAXN];
__device__ uint2 g_bucket[(size_t)MAXN * CAP];  // (col, val_bits) (52 MB)
__device__ int   g_ovf_n;
__device__ int   g_ovf[MAXOVF];

// ---------------------------------------------------------------------------
// helpers
// ---------------------------------------------------------------------------
__device__ __forceinline__ unsigned smem_u32(const void* p) {
    return (unsigned)__cvta_generic_to_shared(p);
}
__device__ __forceinline__ void cp_async16(unsigned dst, const void* src) {
    asm volatile("cp.async.cg.shared.global [%0], [%1], 16;"
                 :: "r"(dst), "l"(src));
}
__device__ __forceinline__ void cp_commit() {
    asm volatile("cp.async.commit_group;");
}
template <int N>
__device__ __forceinline__ void cp_wait() {
    asm volatile("cp.async.wait_group %0;" :: "n"(N));
}
__device__ __forceinline__ unsigned f2tf32(float f) {
    unsigned r;
    asm("cvt.rna.tf32.f32 %0, %1;" : "=r"(r) : "f"(f));
    return r;
}
__device__ __forceinline__ void mma_tf32(float& c0, float& c1, float& c2, float& c3,
                                         unsigned a0, unsigned a1, unsigned a2, unsigned a3,
                                         unsigned b0, unsigned b1) {
    asm volatile("mma.sync.aligned.m16n8k8.row.col.f32.tf32.tf32.f32 "
                 "{%0,%1,%2,%3}, {%4,%5,%6,%7}, {%8,%9}, {%0,%1,%2,%3};"
                 : "+f"(c0), "+f"(c1), "+f"(c2), "+f"(c3)
                 : "r"(a0), "r"(a1), "r"(a2), "r"(a3), "r"(b0), "r"(b1));
}

// ---------------------------------------------------------------------------
// Fused: x = feat @ W (TF32 MMA, R5 config) + edge bucketize INTERLEAVED
// inside the chunk loop (~2 edges/thread/chunk; atomic latency hides under
// the chunk's MMA + cp.async work).
// ---------------------------------------------------------------------------
__global__ __launch_bounds__(NT)
void fused_gemm_scatter_kernel(const float* __restrict__ feat,
                               const float* __restrict__ weight,
                               const float* __restrict__ vals,
                               const int* __restrict__ erow,
                               const int* __restrict__ ecol,
                               int n_nodes, int n_edges, int epb) {
    extern __shared__ char smem[];
    unsigned* sWt = (unsigned*)smem;
    float*    sF  = (float*)(smem + SWT_ELEMS * 4);

    const int t    = threadIdx.x;
    const int warp = t >> 5;
    const int lane = t & 31;
    const int gid  = lane >> 2;
    const int tid4 = lane & 3;
    const int row0 = blockIdx.x * TM;

    // this block's edge slice, split across the 8 chunks
    const int e0   = blockIdx.x * epb;
    const int eup  = min(e0 + epb, n_edges);
    const int epc  = (epb + NCHUNK - 1) / NCHUNK;   // edges per chunk slice

    auto stage = [&](int c, int b) {
        #pragma unroll
        for (int i = 0; i < (TM * 8) / NT; i++) {
            int idx = i * NT + t;
            int r   = idx >> 3;
            int s   = idx & 7;
            int gr  = row0 + r;
            if (gr > n_nodes - 1) gr = n_nodes - 1;
            const float* src = feat + (size_t)gr * IN_FEAT + c * KCH + s * 4;
            cp_async16(smem_u32(&sF[b * SF_ELEMS + r * SFP + s * 4]), src);
        }
        cp_commit();
    };

    auto scatter_slice = [&](int c) {
        int ss = e0 + c * epc;
        int se = min(ss + epc, eup);
        for (int e = ss + t; e < se; e += NT) {
            int r = __ldg(erow + e);
            int cc = __ldg(ecol + e);
            float v = __ldg(vals + e);
            int pos = atomicAdd(&g_cnt[r], 1);
            if (pos < CAP) {
                g_bucket[(size_t)r * CAP + pos] =
                    make_uint2((unsigned)cc, __float_as_uint(v));
            } else {
                int o = atomicAdd(&g_ovf_n, 1);
                if (o < MAXOVF) g_ovf[o] = e;
            }
        }
    };

    stage(0, 0);

    // W -> smem (transposed, tf32)
    #pragma unroll
    for (int i = 0; i < (IN_FEAT * OUT_FEAT) / NT; i++) {
        int idx = i * NT + t;
        int k = idx >> 5;
        int n = idx & 31;
        sWt[n * KP + k] = f2tf32(weight[idx]);
    }

    float acc[2][4][4];
    #pragma unroll
    for (int m = 0; m < 2; m++)
        #pragma unroll
        for (int n = 0; n < 4; n++)
            #pragma unroll
            for (int i = 0; i < 4; i++) acc[m][n][i] = 0.f;

    #pragma unroll 1
    for (int c = 0; c < NCHUNK; c++) {
        int b = c & 1;
        if (c + 1 < NCHUNK) { stage(c + 1, b ^ 1); cp_wait<1>(); }
        else                { cp_wait<0>(); }
        __syncthreads();

        // interleaved scatter: ~2 edges/thread, latency hidden under MMA below
        scatter_slice(c);

        const float* fb = &sF[b * SF_ELEMS];
        #pragma unroll
        for (int ks = 0; ks < KCH / 8; ks++) {
            int kl = ks * 8;
            int kg = c * KCH + kl;

            unsigned bf[4][2];
            #pragma unroll
            for (int n = 0; n < 4; n++) {
                const unsigned* wp = &sWt[(n * 8 + gid) * KP + kg + tid4];
                bf[n][0] = wp[0];
                bf[n][1] = wp[4];
            }

            unsigned af[2][4];
            #pragma unroll
            for (int m = 0; m < 2; m++) {
                int rb = warp * 32 + m * 16 + gid;
                const float* ap0 = &fb[rb * SFP + kl + tid4];
                const float* ap1 = &fb[(rb + 8) * SFP + kl + tid4];
                af[m][0] = f2tf32(ap0[0]);
                af[m][1] = f2tf32(ap1[0]);
                af[m][2] = f2tf32(ap0[4]);
                af[m][3] = f2tf32(ap1[4]);
            }

            #pragma unroll
            for (int n = 0; n < 4; n++)
                #pragma unroll
                for (int m = 0; m < 2; m++)
                    mma_tf32(acc[m][n][0], acc[m][n][1], acc[m][n][2], acc[m][n][3],
                             af[m][0], af[m][1], af[m][2], af[m][3],
                             bf[n][0], bf[n][1]);
        }
        __syncthreads();
    }

    #pragma unroll
    for (int m = 0; m < 2; m++) {
        int r0 = row0 + warp * 32 + m * 16 + gid;
        #pragma unroll
        for (int n = 0; n < 4; n++) {
            int col = n * 8 + 2 * tid4;
            if (r0 < n_nodes) {
                float2 v = make_float2(acc[m][n][0], acc[m][n][1]);
                *(float2*)(g_x + (size_t)r0 * OUT_FEAT + col) = v;
            }
            if (r0 + 8 < n_nodes) {
                float2 v = make_float2(acc[m][n][2], acc[m][n][3]);
                *(float2*)(g_x + (size_t)(r0 + 8) * OUT_FEAT + col) = v;
            }
        }
    }
}

// ---------------------------------------------------------------------------
__global__ void zero_kernel(int n) {
    int i = blockIdx.x * 256 + threadIdx.x;
    if (i < n) g_cnt[i] = 0;
    if (i == 0) g_ovf_n = 0;
}

// ---------------------------------------------------------------------------
// gather: 8 threads/row, 4 cols each; 8-edge batches (R8 config, measured
// 28.1 us) with pair loads widened to uint4 (2 pairs per LDG.128).
// ---------------------------------------------------------------------------
__global__ __launch_bounds__(256)
void gather_kernel(float* __restrict__ out, int n_nodes) {
    int idx = blockIdx.x * 256 + threadIdx.x;
    int row = idx >> 3;
    if (row >= n_nodes) return;
    int q = (idx & 7) << 2;

    int cnt = g_cnt[row];
    if (cnt > CAP) cnt = CAP;
    const uint2* bk = g_bucket + (size_t)row * CAP;
    const uint4* bk4 = (const uint4*)bk;

    float4 acc; acc.x = acc.y = acc.z = acc.w = 0.f;

    int j = 0;
    for (; j + 8 <= cnt; j += 8) {
        uint4 pp[4];
        #pragma unroll
        for (int u = 0; u < 4; u++) pp[u] = bk4[(j >> 1) + u];
        float4 xv[8];
        #pragma unroll
        for (int u = 0; u < 4; u++) {
            xv[2*u]   = *(const float4*)(g_x + (size_t)pp[u].x * OUT_FEAT + q);
            xv[2*u+1] = *(const float4*)(g_x + (size_t)pp[u].z * OUT_FEAT + q);
        }
        #pragma unroll
        for (int u = 0; u < 4; u++) {
            float v0 = __uint_as_float(pp[u].y);
            float v1 = __uint_as_float(pp[u].w);
            acc.x += v0 * xv[2*u].x + v1 * xv[2*u+1].x;
            acc.y += v0 * xv[2*u].y + v1 * xv[2*u+1].y;
            acc.z += v0 * xv[2*u].z + v1 * xv[2*u+1].z;
            acc.w += v0 * xv[2*u].w + v1 * xv[2*u+1].w;
        }
    }
    if (j + 4 <= cnt) {
        uint4 pp[2];
        #pragma unroll
        for (int u = 0; u < 2; u++) pp[u] = bk4[(j >> 1) + u];
        float4 xv[4];
        #pragma unroll
        for (int u = 0; u < 2; u++) {
            xv[2*u]   = *(const float4*)(g_x + (size_t)pp[u].x * OUT_FEAT + q);
            xv[2*u+1] = *(const float4*)(g_x + (size_t)pp[u].z * OUT_FEAT + q);
        }
        #pragma unroll
        for (int u = 0; u < 2; u++) {
            float v0 = __uint_as_float(pp[u].y);
            float v1 = __uint_as_float(pp[u].w);
            acc.x += v0 * xv[2*u].x + v1 * xv[2*u+1].x;
            acc.y += v0 * xv[2*u].y + v1 * xv[2*u+1].y;
            acc.z += v0 * xv[2*u].z + v1 * xv[2*u+1].z;
            acc.w += v0 * xv[2*u].w + v1 * xv[2*u+1].w;
        }
        j += 4;
    }
    for (; j < cnt; j++) {
        uint2 p = bk[j];
        float4 xv = *(const float4*)(g_x + (size_t)p.x * OUT_FEAT + q);
        float v = __uint_as_float(p.y);
        acc.x += v * xv.x; acc.y += v * xv.y;
        acc.z += v * xv.z; acc.w += v * xv.w;
    }

    *(float4*)(out + (size_t)row * OUT_FEAT + q) = acc;
}

// ---------------------------------------------------------------------------
// overflow fixup (expected empty at CAP=64; parallel across 32 blocks)
// ---------------------------------------------------------------------------
__global__ void fixup_kernel(const float* __restrict__ vals,
                             const int* __restrict__ erow,
                             const int* __restrict__ ecol,
                             float* __restrict__ out) {
    int n = g_ovf_n;
    if (n > MAXOVF) n = MAXOVF;
    int gidx = blockIdx.x * 256 + threadIdx.x;
    for (int i = gidx; i < n * 8; i += gridDim.x * 256) {
        int e = g_ovf[i >> 3];
        int q = (i & 7) << 2;
        int r = erow[e], c = ecol[e];
        float v = vals[e];
        #pragma unroll
        for (int k = 0; k < 4; k++)
            atomicAdd(&out[(size_t)r * OUT_FEAT + q + k],
                      v * g_x[(size_t)c * OUT_FEAT + q + k]);
    }
}

// ---------------------------------------------------------------------------
extern "C" void kernel_launch(void* const* d_in, const int* in_sizes, int n_in,
                              void* d_out, int out_size) {
    const float* feat   = (const float*)d_in[0];
    const float* weight = (const float*)d_in[1];
    const float* vals   = (const float*)d_in[2];
    const int*   erow   = (const int*)d_in[3];
    const int*   ecol   = (const int*)d_in[4];
    float* out = (float*)d_out;

    int n_nodes = in_sizes[0] / IN_FEAT;
    int n_edges = in_sizes[2];

    cudaFuncSetAttribute(fused_gemm_scatter_kernel,
                         cudaFuncAttributeMaxDynamicSharedMemorySize, SMEM_BYTES);

    int nb_nodes    = (n_nodes + 255) / 256;
    int gemm_blocks = (n_nodes + TM - 1) / TM;
    int epb         = (n_edges + gemm_blocks - 1) / gemm_blocks;

    zero_kernel<<<nb_nodes, 256>>>(n_nodes);

    fused_gemm_scatter_kernel<<<gemm_blocks, NT, SMEM_BYTES>>>(
        feat, weight, vals, erow, ecol, n_nodes, n_edges, epb);

    long long gw = (long long)n_nodes * 8;
    int nb_gather = (int)((gw + 255) / 256);
    gather_kernel<<<nb_gather, 256>>>(out, n_nodes);

    fixup_kernel<<<32, 256>>>(vals, erow, ecol, out);
}

// round 12
// speedup vs baseline: 1.3255x; 1.3255x over previous
#include <cuda_runtime.h>
#include <cuda_bf16.h>
#include <cstdint>

#define IN_FEAT   256
#define OUT_FEAT  32
#define MAXN      102400
#define CAP       64             // bucket slots per row (avg degree 16)
#define MAXOVF    8192
#define TM        256
#define NT        256
#define KCH       32             // k-floats per staged chunk
#define NCHUNK    (IN_FEAT / KCH)   // 8
#define SFP       36
#define KP        260
#define SWT_ELEMS (OUT_FEAT * KP)
#define SF_ELEMS  (TM * SFP)
#define SMEM_BYTES ((SWT_ELEMS + 2 * SF_ELEMS) * 4)   // ~105 KB -> 2 blocks/SM

__device__ float g_x[MAXN * OUT_FEAT];          // projected features (13 MB)
__device__ int   g_cnt[MAXN];
__device__ uint2 g_bucket[(size_t)MAXN * CAP];  // (col, val_bits) (52 MB)
__device__ int   g_ovf_n;
__device__ int   g_ovf[MAXOVF];

// ---------------------------------------------------------------------------
// helpers
// ---------------------------------------------------------------------------
__device__ __forceinline__ unsigned smem_u32(const void* p) {
    return (unsigned)__cvta_generic_to_shared(p);
}
__device__ __forceinline__ void cp_async16(unsigned dst, const void* src) {
    asm volatile("cp.async.cg.shared.global [%0], [%1], 16;"
                 :: "r"(dst), "l"(src));
}
__device__ __forceinline__ void cp_commit() {
    asm volatile("cp.async.commit_group;");
}
template <int N>
__device__ __forceinline__ void cp_wait() {
    asm volatile("cp.async.wait_group %0;" :: "n"(N));
}
__device__ __forceinline__ unsigned f2tf32(float f) {
    unsigned r;
    asm("cvt.rna.tf32.f32 %0, %1;" : "=r"(r) : "f"(f));
    return r;
}
__device__ __forceinline__ void mma_tf32(float& c0, float& c1, float& c2, float& c3,
                                         unsigned a0, unsigned a1, unsigned a2, unsigned a3,
                                         unsigned b0, unsigned b1) {
    asm volatile("mma.sync.aligned.m16n8k8.row.col.f32.tf32.tf32.f32 "
                 "{%0,%1,%2,%3}, {%4,%5,%6,%7}, {%8,%9}, {%0,%1,%2,%3};"
                 : "+f"(c0), "+f"(c1), "+f"(c2), "+f"(c3)
                 : "r"(a0), "r"(a1), "r"(a2), "r"(a3), "r"(b0), "r"(b1));
}

// ---------------------------------------------------------------------------
// Stage 1: x = feat @ W  (TF32 MMA, R5 config).  launch_bounds(256,3) caps
// regs at 85 so the 2 resident blocks leave ~21K registers + 48 warp slots
// per SM free for co-resident scatter blocks (R7's fork couldn't overlap
// because default reg allocation consumed the entire register file).
// ---------------------------------------------------------------------------
__global__ __launch_bounds__(NT, 3)
void gemm_kernel(const float* __restrict__ feat,
                 const float* __restrict__ weight,
                 int n_nodes) {
    extern __shared__ char smem[];
    unsigned* sWt = (unsigned*)smem;
    float*    sF  = (float*)(smem + SWT_ELEMS * 4);

    const int t    = threadIdx.x;
    const int warp = t >> 5;
    const int lane = t & 31;
    const int gid  = lane >> 2;
    const int tid4 = lane & 3;
    const int row0 = blockIdx.x * TM;

    auto stage = [&](int c, int b) {
        #pragma unroll
        for (int i = 0; i < (TM * 8) / NT; i++) {
            int idx = i * NT + t;
            int r   = idx >> 3;
            int s   = idx & 7;
            int gr  = row0 + r;
            if (gr > n_nodes - 1) gr = n_nodes - 1;
            const float* src = feat + (size_t)gr * IN_FEAT + c * KCH + s * 4;
            cp_async16(smem_u32(&sF[b * SF_ELEMS + r * SFP + s * 4]), src);
        }
        cp_commit();
    };

    stage(0, 0);

    #pragma unroll
    for (int i = 0; i < (IN_FEAT * OUT_FEAT) / NT; i++) {
        int idx = i * NT + t;
        int k = idx >> 5;
        int n = idx & 31;
        sWt[n * KP + k] = f2tf32(weight[idx]);
    }

    float acc[2][4][4];
    #pragma unroll
    for (int m = 0; m < 2; m++)
        #pragma unroll
        for (int n = 0; n < 4; n++)
            #pragma unroll
            for (int i = 0; i < 4; i++) acc[m][n][i] = 0.f;

    #pragma unroll 1
    for (int c = 0; c < NCHUNK; c++) {
        int b = c & 1;
        if (c + 1 < NCHUNK) { stage(c + 1, b ^ 1); cp_wait<1>(); }
        else                { cp_wait<0>(); }
        __syncthreads();

        const float* fb = &sF[b * SF_ELEMS];
        #pragma unroll
        for (int ks = 0; ks < KCH / 8; ks++) {
            int kl = ks * 8;
            int kg = c * KCH + kl;

            unsigned bf[4][2];
            #pragma unroll
            for (int n = 0; n < 4; n++) {
                const unsigned* wp = &sWt[(n * 8 + gid) * KP + kg + tid4];
                bf[n][0] = wp[0];
                bf[n][1] = wp[4];
            }

            unsigned af[2][4];
            #pragma unroll
            for (int m = 0; m < 2; m++) {
                int rb = warp * 32 + m * 16 + gid;
                const float* ap0 = &fb[rb * SFP + kl + tid4];
                const float* ap1 = &fb[(rb + 8) * SFP + kl + tid4];
                af[m][0] = f2tf32(ap0[0]);
                af[m][1] = f2tf32(ap1[0]);
                af[m][2] = f2tf32(ap0[4]);
                af[m][3] = f2tf32(ap1[4]);
            }

            #pragma unroll
            for (int n = 0; n < 4; n++)
                #pragma unroll
                for (int m = 0; m < 2; m++)
                    mma_tf32(acc[m][n][0], acc[m][n][1], acc[m][n][2], acc[m][n][3],
                             af[m][0], af[m][1], af[m][2], af[m][3],
                             bf[n][0], bf[n][1]);
        }
        __syncthreads();
    }

    #pragma unroll
    for (int m = 0; m < 2; m++) {
        int r0 = row0 + warp * 32 + m * 16 + gid;
        #pragma unroll
        for (int n = 0; n < 4; n++) {
            int col = n * 8 + 2 * tid4;
            if (r0 < n_nodes) {
                float2 v = make_float2(acc[m][n][0], acc[m][n][1]);
                *(float2*)(g_x + (size_t)r0 * OUT_FEAT + col) = v;
            }
            if (r0 + 8 < n_nodes) {
                float2 v = make_float2(acc[m][n][2], acc[m][n][3]);
                *(float2*)(g_x + (size_t)(r0 + 8) * OUT_FEAT + col) = v;
            }
        }
    }
}

// ---------------------------------------------------------------------------
__global__ void zero_kernel(int n) {
    int i = blockIdx.x * 256 + threadIdx.x;
    if (i < n) g_cnt[i] = 0;
    if (i == 0) g_ovf_n = 0;
}

// ---------------------------------------------------------------------------
// bucketize: simple 1-edge form (R7-proven; batched variants regressed)
// ---------------------------------------------------------------------------
__global__ __launch_bounds__(256)
void scatter_kernel(const float* __restrict__ vals,
                    const int* __restrict__ erow,
                    const int* __restrict__ ecol,
                    int n_edges) {
    int e = blockIdx.x * 256 + threadIdx.x;
    if (e >= n_edges) return;
    int r = __ldg(erow + e);
    int c = __ldg(ecol + e);
    float v = __ldg(vals + e);
    int pos = atomicAdd(&g_cnt[r], 1);
    if (pos < CAP) {
        g_bucket[(size_t)r * CAP + pos] =
            make_uint2((unsigned)c, __float_as_uint(v));
    } else {
        int o = atomicAdd(&g_ovf_n, 1);
        if (o < MAXOVF) g_ovf[o] = e;
    }
}

// ---------------------------------------------------------------------------
// gather: R8-exact (8 thr/row, 4 cols, 8-edge batches; measured 28.1 us)
// ---------------------------------------------------------------------------
__global__ __launch_bounds__(256)
void gather_kernel(float* __restrict__ out, int n_nodes) {
    int idx = blockIdx.x * 256 + threadIdx.x;
    int row = idx >> 3;
    if (row >= n_nodes) return;
    int q = (idx & 7) << 2;

    int cnt = g_cnt[row];
    if (cnt > CAP) cnt = CAP;
    const uint2* bk = g_bucket + (size_t)row * CAP;

    float4 acc; acc.x = acc.y = acc.z = acc.w = 0.f;

    int j = 0;
    for (; j + 8 <= cnt; j += 8) {
        uint2 p[8];
        #pragma unroll
        for (int u = 0; u < 8; u++) p[u] = bk[j + u];
        float4 xv[8];
        #pragma unroll
        for (int u = 0; u < 8; u++)
            xv[u] = *(const float4*)(g_x + (size_t)p[u].x * OUT_FEAT + q);
        #pragma unroll
        for (int u = 0; u < 8; u++) {
            float v = __uint_as_float(p[u].y);
            acc.x += v * xv[u].x; acc.y += v * xv[u].y;
            acc.z += v * xv[u].z; acc.w += v * xv[u].w;
        }
    }
    if (j + 4 <= cnt) {
        uint2 p[4];
        #pragma unroll
        for (int u = 0; u < 4; u++) p[u] = bk[j + u];
        float4 xv[4];
        #pragma unroll
        for (int u = 0; u < 4; u++)
            xv[u] = *(const float4*)(g_x + (size_t)p[u].x * OUT_FEAT + q);
        #pragma unroll
        for (int u = 0; u < 4; u++) {
            float v = __uint_as_float(p[u].y);
            acc.x += v * xv[u].x; acc.y += v * xv[u].y;
            acc.z += v * xv[u].z; acc.w += v * xv[u].w;
        }
        j += 4;
    }
    for (; j < cnt; j++) {
        uint2 p = bk[j];
        float4 xv = *(const float4*)(g_x + (size_t)p.x * OUT_FEAT + q);
        float v = __uint_as_float(p.y);
        acc.x += v * xv.x; acc.y += v * xv.y;
        acc.z += v * xv.z; acc.w += v * xv.w;
    }

    *(float4*)(out + (size_t)row * OUT_FEAT + q) = acc;
}

// ---------------------------------------------------------------------------
// overflow fixup (expected empty at CAP=64; parallel)
// ---------------------------------------------------------------------------
__global__ void fixup_kernel(const float* __restrict__ vals,
                             const int* __restrict__ erow,
                             const int* __restrict__ ecol,
                             float* __restrict__ out) {
    int n = g_ovf_n;
    if (n > MAXOVF) n = MAXOVF;
    int gidx = blockIdx.x * 256 + threadIdx.x;
    for (int i = gidx; i < n * 8; i += gridDim.x * 256) {
        int e = g_ovf[i >> 3];
        int q = (i & 7) << 2;
        int r = erow[e], c = ecol[e];
        float v = vals[e];
        #pragma unroll
        for (int k = 0; k < 4; k++)
            atomicAdd(&out[(size_t)r * OUT_FEAT + q + k],
                      v * g_x[(size_t)c * OUT_FEAT + q + k]);
    }
}

// ---------------------------------------------------------------------------
extern "C" void kernel_launch(void* const* d_in, const int* in_sizes, int n_in,
                              void* d_out, int out_size) {
    const float* feat   = (const float*)d_in[0];
    const float* weight = (const float*)d_in[1];
    const float* vals   = (const float*)d_in[2];
    const int*   erow   = (const int*)d_in[3];
    const int*   ecol   = (const int*)d_in[4];
    float* out = (float*)d_out;

    int n_nodes = in_sizes[0] / IN_FEAT;
    int n_edges = in_sizes[2];

    static cudaStream_t s2 = nullptr;
    static cudaEvent_t  evFork = nullptr, evJoin = nullptr;
    if (!s2) {
        cudaStreamCreateWithFlags(&s2, cudaStreamNonBlocking);
        cudaEventCreateWithFlags(&evFork, cudaEventDisableTiming);
        cudaEventCreateWithFlags(&evJoin, cudaEventDisableTiming);
    }

    cudaFuncSetAttribute(gemm_kernel,
                         cudaFuncAttributeMaxDynamicSharedMemorySize, SMEM_BYTES);

    int nb_nodes    = (n_nodes + 255) / 256;
    int nb_edges    = (n_edges + 255) / 256;
    int gemm_blocks = (n_nodes + TM - 1) / TM;

    // fork: scatter path captured FIRST on the main stream (dispatch priority);
    // gemm runs on s2 and backfills / co-resides (reg-capped to leave RF room).
    cudaEventRecord(evFork, 0);
    cudaStreamWaitEvent(s2, evFork, 0);

    zero_kernel<<<nb_nodes, 256>>>(n_nodes);
    scatter_kernel<<<nb_edges, 256>>>(vals, erow, ecol, n_edges);

    gemm_kernel<<<gemm_blocks, NT, SMEM_BYTES, s2>>>(feat, weight, n_nodes);

    cudaEventRecord(evJoin, s2);
    cudaStreamWaitEvent(0, evJoin, 0);

    long long gw = (long long)n_nodes * 8;
    int nb_gather = (int)((gw + 255) / 256);
    gather_kernel<<<nb_gather, 256>>>(out, n_nodes);

    fixup_kernel<<<32, 256>>>(vals, erow, ecol, out);
}

// round 13
// speedup vs baseline: 1.3632x; 1.0285x over previous
#include <cuda_runtime.h>
#include <cuda_bf16.h>
#include <cstdint>

#define IN_FEAT   256
#define OUT_FEAT  32
#define MAXN      102400
#define CAP       64             // bucket slots per row (avg degree 16)
#define MAXOVF    8192
#define TM        256
#define NT        256
#define KCH       32
#define NCHUNK    (IN_FEAT / KCH)   // 8
#define SFP       36
#define KP        260
#define SWT_ELEMS (OUT_FEAT * KP)
#define SF_ELEMS  (TM * SFP)
#define SMEM_BYTES ((SWT_ELEMS + 2 * SF_ELEMS) * 4)

__device__ float g_x[MAXN * OUT_FEAT];          // projected features (13 MB)
__device__ int   g_cnt[MAXN];
__device__ uint2 g_bucket[(size_t)MAXN * CAP];  // (col, val_bits) (52 MB)
__device__ int   g_ovf_n;
__device__ int   g_ovf[MAXOVF];

// ---------------------------------------------------------------------------
// helpers
// ---------------------------------------------------------------------------
__device__ __forceinline__ unsigned smem_u32(const void* p) {
    return (unsigned)__cvta_generic_to_shared(p);
}
__device__ __forceinline__ void cp_async16(unsigned dst, const void* src) {
    asm volatile("cp.async.cg.shared.global [%0], [%1], 16;"
                 :: "r"(dst), "l"(src));
}
__device__ __forceinline__ void cp_commit() {
    asm volatile("cp.async.commit_group;");
}
template <int N>
__device__ __forceinline__ void cp_wait() {
    asm volatile("cp.async.wait_group %0;" :: "n"(N));
}
__device__ __forceinline__ unsigned f2tf32(float f) {
    unsigned r;
    asm("cvt.rna.tf32.f32 %0, %1;" : "=r"(r) : "f"(f));
    return r;
}
__device__ __forceinline__ void mma_tf32(float& c0, float& c1, float& c2, float& c3,
                                         unsigned a0, unsigned a1, unsigned a2, unsigned a3,
                                         unsigned b0, unsigned b1) {
    asm volatile("mma.sync.aligned.m16n8k8.row.col.f32.tf32.tf32.f32 "
                 "{%0,%1,%2,%3}, {%4,%5,%6,%7}, {%8,%9}, {%0,%1,%2,%3};"
                 : "+f"(c0), "+f"(c1), "+f"(c2), "+f"(c3)
                 : "r"(a0), "r"(a1), "r"(a2), "r"(a3), "r"(b0), "r"(b1));
}

// ---------------------------------------------------------------------------
// Stage 1: x = feat @ W   (TF32 MMA, R5-exact config, ~27 us)
// ---------------------------------------------------------------------------
__global__ __launch_bounds__(NT)
void gemm_kernel(const float* __restrict__ feat,
                 const float* __restrict__ weight,
                 int n_nodes) {
    extern __shared__ char smem[];
    unsigned* sWt = (unsigned*)smem;
    float*    sF  = (float*)(smem + SWT_ELEMS * 4);

    const int t    = threadIdx.x;
    const int warp = t >> 5;
    const int lane = t & 31;
    const int gid  = lane >> 2;
    const int tid4 = lane & 3;
    const int row0 = blockIdx.x * TM;

    auto stage = [&](int c, int b) {
        #pragma unroll
        for (int i = 0; i < (TM * 8) / NT; i++) {
            int idx = i * NT + t;
            int r   = idx >> 3;
            int s   = idx & 7;
            int gr  = row0 + r;
            if (gr > n_nodes - 1) gr = n_nodes - 1;
            const float* src = feat + (size_t)gr * IN_FEAT + c * KCH + s * 4;
            cp_async16(smem_u32(&sF[b * SF_ELEMS + r * SFP + s * 4]), src);
        }
        cp_commit();
    };

    stage(0, 0);

    #pragma unroll
    for (int i = 0; i < (IN_FEAT * OUT_FEAT) / NT; i++) {
        int idx = i * NT + t;
        int k = idx >> 5;
        int n = idx & 31;
        sWt[n * KP + k] = f2tf32(weight[idx]);
    }

    float acc[2][4][4];
    #pragma unroll
    for (int m = 0; m < 2; m++)
        #pragma unroll
        for (int n = 0; n < 4; n++)
            #pragma unroll
            for (int i = 0; i < 4; i++) acc[m][n][i] = 0.f;

    #pragma unroll 1
    for (int c = 0; c < NCHUNK; c++) {
        int b = c & 1;
        if (c + 1 < NCHUNK) { stage(c + 1, b ^ 1); cp_wait<1>(); }
        else                { cp_wait<0>(); }
        __syncthreads();

        const float* fb = &sF[b * SF_ELEMS];
        #pragma unroll
        for (int ks = 0; ks < KCH / 8; ks++) {
            int kl = ks * 8;
            int kg = c * KCH + kl;

            unsigned bf[4][2];
            #pragma unroll
            for (int n = 0; n < 4; n++) {
                const unsigned* wp = &sWt[(n * 8 + gid) * KP + kg + tid4];
                bf[n][0] = wp[0];
                bf[n][1] = wp[4];
            }

            unsigned af[2][4];
            #pragma unroll
            for (int m = 0; m < 2; m++) {
                int rb = warp * 32 + m * 16 + gid;
                const float* ap0 = &fb[rb * SFP + kl + tid4];
                const float* ap1 = &fb[(rb + 8) * SFP + kl + tid4];
                af[m][0] = f2tf32(ap0[0]);
                af[m][1] = f2tf32(ap1[0]);
                af[m][2] = f2tf32(ap0[4]);
                af[m][3] = f2tf32(ap1[4]);
            }

            #pragma unroll
            for (int n = 0; n < 4; n++)
                #pragma unroll
                for (int m = 0; m < 2; m++)
                    mma_tf32(acc[m][n][0], acc[m][n][1], acc[m][n][2], acc[m][n][3],
                             af[m][0], af[m][1], af[m][2], af[m][3],
                             bf[n][0], bf[n][1]);
        }
        __syncthreads();
    }

    #pragma unroll
    for (int m = 0; m < 2; m++) {
        int r0 = row0 + warp * 32 + m * 16 + gid;
        #pragma unroll
        for (int n = 0; n < 4; n++) {
            int col = n * 8 + 2 * tid4;
            if (r0 < n_nodes) {
                float2 v = make_float2(acc[m][n][0], acc[m][n][1]);
                *(float2*)(g_x + (size_t)r0 * OUT_FEAT + col) = v;
            }
            if (r0 + 8 < n_nodes) {
                float2 v = make_float2(acc[m][n][2], acc[m][n][3]);
                *(float2*)(g_x + (size_t)(r0 + 8) * OUT_FEAT + col) = v;
            }
        }
    }
}

// ---------------------------------------------------------------------------
__global__ void zero_kernel(int n) {
    int i = blockIdx.x * 256 + threadIdx.x;
    if (i < n) g_cnt[i] = 0;
    if (i == 0) g_ovf_n = 0;
}

// ---------------------------------------------------------------------------
// bucketize: 4 CONSECUTIVE edges per thread, vectorized inputs.
// LSU ops per 4 edges: 3 LDG.128 + 4 ATOMG + 4 STG.64 = 11 (was 20).
// n_edges is divisible by 4 here (1.6M); tail guard kept for safety.
// ---------------------------------------------------------------------------
__global__ __launch_bounds__(256)
void scatter_kernel(const float* __restrict__ vals,
                    const int* __restrict__ erow,
                    const int* __restrict__ ecol,
                    int n_edges) {
    int idx = blockIdx.x * 256 + threadIdx.x;
    int e = idx * 4;
    if (e + 3 < n_edges) {
        int4   r4 = *(const int4*)(erow + e);
        int4   c4 = *(const int4*)(ecol + e);
        float4 v4 = *(const float4*)(vals + e);
        int r[4] = {r4.x, r4.y, r4.z, r4.w};
        int c[4] = {c4.x, c4.y, c4.z, c4.w};
        float v[4] = {v4.x, v4.y, v4.z, v4.w};
        int pos[4];
        #pragma unroll
        for (int i = 0; i < 4; i++)
            pos[i] = atomicAdd(&g_cnt[r[i]], 1);
        #pragma unroll
        for (int i = 0; i < 4; i++) {
            if (pos[i] < CAP) {
                g_bucket[(size_t)r[i] * CAP + pos[i]] =
                    make_uint2((unsigned)c[i], __float_as_uint(v[i]));
            } else {
                int o = atomicAdd(&g_ovf_n, 1);
                if (o < MAXOVF) g_ovf[o] = e + i;
            }
        }
    } else {
        for (int i = 0; i < 4; i++) {
            int ee = e + i;
            if (ee >= n_edges) break;
            int r = __ldg(erow + ee);
            int c = __ldg(ecol + ee);
            float v = __ldg(vals + ee);
            int pos = atomicAdd(&g_cnt[r], 1);
            if (pos < CAP) {
                g_bucket[(size_t)r * CAP + pos] =
                    make_uint2((unsigned)c, __float_as_uint(v));
            } else {
                int o = atomicAdd(&g_ovf_n, 1);
                if (o < MAXOVF) g_ovf[o] = ee;
            }
        }
    }
}

// ---------------------------------------------------------------------------
// gather: R8 shape (8 thr/row, 4 cols, 8-edge batches) with uint4 pair loads
// (2 pairs per LDG.128 -> pair LSU ops halved).
// ---------------------------------------------------------------------------
__global__ __launch_bounds__(256)
void gather_kernel(float* __restrict__ out, int n_nodes) {
    int idx = blockIdx.x * 256 + threadIdx.x;
    int row = idx >> 3;
    if (row >= n_nodes) return;
    int q = (idx & 7) << 2;

    int cnt = g_cnt[row];
    if (cnt > CAP) cnt = CAP;
    const uint2* bk = g_bucket + (size_t)row * CAP;
    const uint4* bk4 = (const uint4*)bk;

    float4 acc; acc.x = acc.y = acc.z = acc.w = 0.f;

    int j = 0;
    for (; j + 8 <= cnt; j += 8) {
        uint4 pp[4];
        #pragma unroll
        for (int u = 0; u < 4; u++) pp[u] = bk4[(j >> 1) + u];
        float4 xv[8];
        #pragma unroll
        for (int u = 0; u < 4; u++) {
            xv[2*u]   = *(const float4*)(g_x + (size_t)pp[u].x * OUT_FEAT + q);
            xv[2*u+1] = *(const float4*)(g_x + (size_t)pp[u].z * OUT_FEAT + q);
        }
        #pragma unroll
        for (int u = 0; u < 4; u++) {
            float v0 = __uint_as_float(pp[u].y);
            float v1 = __uint_as_float(pp[u].w);
            acc.x += v0 * xv[2*u].x + v1 * xv[2*u+1].x;
            acc.y += v0 * xv[2*u].y + v1 * xv[2*u+1].y;
            acc.z += v0 * xv[2*u].z + v1 * xv[2*u+1].z;
            acc.w += v0 * xv[2*u].w + v1 * xv[2*u+1].w;
        }
    }
    if (j + 4 <= cnt) {
        uint4 pp[2];
        #pragma unroll
        for (int u = 0; u < 2; u++) pp[u] = bk4[(j >> 1) + u];
        float4 xv[4];
        #pragma unroll
        for (int u = 0; u < 2; u++) {
            xv[2*u]   = *(const float4*)(g_x + (size_t)pp[u].x * OUT_FEAT + q);
            xv[2*u+1] = *(const float4*)(g_x + (size_t)pp[u].z * OUT_FEAT + q);
        }
        #pragma unroll
        for (int u = 0; u < 2; u++) {
            float v0 = __uint_as_float(pp[u].y);
            float v1 = __uint_as_float(pp[u].w);
            acc.x += v0 * xv[2*u].x + v1 * xv[2*u+1].x;
            acc.y += v0 * xv[2*u].y + v1 * xv[2*u+1].y;
            acc.z += v0 * xv[2*u].z + v1 * xv[2*u+1].z;
            acc.w += v0 * xv[2*u].w + v1 * xv[2*u+1].w;
        }
        j += 4;
    }
    for (; j < cnt; j++) {
        uint2 p = bk[j];
        float4 xv = *(const float4*)(g_x + (size_t)p.x * OUT_FEAT + q);
        float v = __uint_as_float(p.y);
        acc.x += v * xv.x; acc.y += v * xv.y;
        acc.z += v * xv.z; acc.w += v * xv.w;
    }

    *(float4*)(out + (size_t)row * OUT_FEAT + q) = acc;
}

// ---------------------------------------------------------------------------
// overflow fixup (expected empty at CAP=64)
// ---------------------------------------------------------------------------
__global__ void fixup_kernel(const float* __restrict__ vals,
                             const int* __restrict__ erow,
                             const int* __restrict__ ecol,
                             float* __restrict__ out) {
    int n = g_ovf_n;
    if (n > MAXOVF) n = MAXOVF;
    int gidx = blockIdx.x * 256 + threadIdx.x;
    for (int i = gidx; i < n * 8; i += gridDim.x * 256) {
        int e = g_ovf[i >> 3];
        int q = (i & 7) << 2;
        int r = erow[e], c = ecol[e];
        float v = vals[e];
        #pragma unroll
        for (int k = 0; k < 4; k++)
            atomicAdd(&out[(size_t)r * OUT_FEAT + q + k],
                      v * g_x[(size_t)c * OUT_FEAT + q + k]);
    }
}

// ---------------------------------------------------------------------------
extern "C" void kernel_launch(void* const* d_in, const int* in_sizes, int n_in,
                              void* d_out, int out_size) {
    const float* feat   = (const float*)d_in[0];
    const float* weight = (const float*)d_in[1];
    const float* vals   = (const float*)d_in[2];
    const int*   erow   = (const int*)d_in[3];
    const int*   ecol   = (const int*)d_in[4];
    float* out = (float*)d_out;

    int n_nodes = in_sizes[0] / IN_FEAT;
    int n_edges = in_sizes[2];

    cudaFuncSetAttribute(gemm_kernel,
                         cudaFuncAttributeMaxDynamicSharedMemorySize, SMEM_BYTES);

    int nb_nodes    = (n_nodes + 255) / 256;
    int nb_scat     = (n_edges + 1023) / 1024;
    int gemm_blocks = (n_nodes + TM - 1) / TM;

    zero_kernel<<<nb_nodes, 256>>>(n_nodes);
    scatter_kernel<<<nb_scat, 256>>>(vals, erow, ecol, n_edges);
    gemm_kernel<<<gemm_blocks, NT, SMEM_BYTES>>>(feat, weight, n_nodes);

    long long gw = (long long)n_nodes * 8;
    int nb_gather = (int)((gw + 255) / 256);
    gather_kernel<<<nb_gather, 256>>>(out, n_nodes);

    fixup_kernel<<<32, 256>>>(vals, erow, ecol, out);
}